// round 1
// baseline (speedup 1.0000x reference)
#include <cuda_runtime.h>
#include <math.h>

// Problem constants (fixed by reference setup_inputs)
constexpr int B = 64;
constexpr int I = 2048;
constexpr int P = 16;
constexpr int J = 32;          // == warp size: lane j owns capsule j
constexpr int D = 16;
constexpr int JD = J * D;      // 512
constexpr int NIB = 32;        // i-blocks per (b) for routing
constexpr int IPB = I / NIB;   // 64 i's per CTA

// Scratch (device globals; no allocation allowed)
__device__ float g_uhat[(size_t)B * I * JD];   // 256 MB  [b,i,j,d]
__device__ float g_b[(size_t)B * I * J];       // 16 MB   routing logits
__device__ float g_s[B * J * D];               // 128 KB  s accumulator
__device__ float g_v[B * J * D];               // 128 KB  current v

// ---------------------------------------------------------------------------
// Kernel 1: u_hat[b,i,j,d] = sum_p inputs[b,i,p] * W[i, jd, p]
// One CTA per i. W[i] (32KB) + inputs[:,i,:] (4KB) staged in smem,
// reused across all 64 batches. Thread t computes jd = t and t+256.
// ---------------------------------------------------------------------------
__global__ __launch_bounds__(256) void gemm_uhat(const float* __restrict__ in,
                                                 const float* __restrict__ W) {
    const int i = blockIdx.x;
    const int t = threadIdx.x;

    __shared__ float Ws[JD * P];   // 8192 floats = 32KB, layout [jd][p]
    __shared__ float ins[B * P];   // 1024 floats = 4KB,  layout [b][p]

    // stage W[i]
    const float4* Wg  = reinterpret_cast<const float4*>(W + (size_t)i * JD * P);
    float4* Ws4 = reinterpret_cast<float4*>(Ws);
#pragma unroll
    for (int k = 0; k < 8; k++) Ws4[t + k * 256] = Wg[t + k * 256];

    // stage inputs[:, i, :]
#pragma unroll
    for (int k = 0; k < 4; k++) {
        int e = t + k * 256;               // 0..1023
        int b = e >> 4, p = e & 15;
        ins[e] = in[((size_t)b * I + i) * P + p];
    }
    __syncthreads();

    // per-thread W rows in registers
    float w0[16], w1[16];
#pragma unroll
    for (int p = 0; p < 16; p++) {
        w0[p] = Ws[t * 16 + p];
        w1[p] = Ws[(t + 256) * 16 + p];
    }

    const float4* ins4 = reinterpret_cast<const float4*>(ins);
    for (int b = 0; b < B; b++) {
        float x[16];
        float4 q;
        q = ins4[b * 4 + 0]; x[0]=q.x; x[1]=q.y; x[2]=q.z; x[3]=q.w;
        q = ins4[b * 4 + 1]; x[4]=q.x; x[5]=q.y; x[6]=q.z; x[7]=q.w;
        q = ins4[b * 4 + 2]; x[8]=q.x; x[9]=q.y; x[10]=q.z; x[11]=q.w;
        q = ins4[b * 4 + 3]; x[12]=q.x; x[13]=q.y; x[14]=q.z; x[15]=q.w;

        float a0 = 0.f, a1 = 0.f;
#pragma unroll
        for (int p = 0; p < 16; p++) {
            a0 = fmaf(x[p], w0[p], a0);
            a1 = fmaf(x[p], w1[p], a1);
        }
        size_t base = ((size_t)b * I + i) * JD;
        g_uhat[base + t]       = a0;   // coalesced across threads
        g_uhat[base + t + 256] = a1;
    }
}

// ---------------------------------------------------------------------------
// Kernel 2: one fused routing step.
//   MODE 0: c = 1/32 (softmax of zeros). No b, no v.
//   MODE 1: b_new = u.v (b_prev == 0), write b, c = softmax(b_new)
//   MODE 2: b_new = b_prev + u.v, no write, c = softmax(b_new)
// Then s[b,j,:] += sum_i c[b,i,j] * u_hat[b,i,j,:]  (hierarchical reduction)
// Grid: (NIB, B); 256 threads = 8 warps; lane == j; warp strides over i.
// ---------------------------------------------------------------------------
template <int MODE>
__global__ __launch_bounds__(256) void routing_step() {
    const int b  = blockIdx.y;
    const int ib = blockIdx.x;
    const int w  = threadIdx.x >> 5;
    const int j  = threadIdx.x & 31;

    __shared__ float sacc[J][D + 1];   // +1 pad: conflict-free atomics

    for (int e = threadIdx.x; e < J * (D + 1); e += 256)
        (&sacc[0][0])[e] = 0.f;

    // v[b,j,:] in registers (per-lane; heavily L1/L2 cached, tiny)
    float v[16];
    if (MODE > 0) {
        const float4* vp = reinterpret_cast<const float4*>(g_v + (b * J + j) * D);
        float4 q;
        q = vp[0]; v[0]=q.x; v[1]=q.y; v[2]=q.z; v[3]=q.w;
        q = vp[1]; v[4]=q.x; v[5]=q.y; v[6]=q.z; v[7]=q.w;
        q = vp[2]; v[8]=q.x; v[9]=q.y; v[10]=q.z; v[11]=q.w;
        q = vp[3]; v[12]=q.x; v[13]=q.y; v[14]=q.z; v[15]=q.w;
    }
    __syncthreads();

    float acc[16];
#pragma unroll
    for (int d = 0; d < 16; d++) acc[d] = 0.f;

    for (int ii = w; ii < IPB; ii += 8) {
        const int i = ib * IPB + ii;
        const size_t base = ((size_t)b * I + i) * JD + j * D;
        const float4* up = reinterpret_cast<const float4*>(g_uhat + base);
        float u[16];
        float4 q;
        q = up[0]; u[0]=q.x; u[1]=q.y; u[2]=q.z; u[3]=q.w;
        q = up[1]; u[4]=q.x; u[5]=q.y; u[6]=q.z; u[7]=q.w;
        q = up[2]; u[8]=q.x; u[9]=q.y; u[10]=q.z; u[11]=q.w;
        q = up[3]; u[12]=q.x; u[13]=q.y; u[14]=q.z; u[15]=q.w;

        float c;
        if (MODE == 0) {
            c = 1.f / 32.f;
        } else {
            float tdot = 0.f;
#pragma unroll
            for (int d = 0; d < 16; d++) tdot = fmaf(u[d], v[d], tdot);

            float bn;
            if (MODE == 1) {
                bn = tdot;
                g_b[((size_t)b * I + i) * J + j] = bn;   // coalesced
            } else {
                bn = g_b[((size_t)b * I + i) * J + j] + tdot;
            }
            // warp softmax over j (32 lanes)
            float m = bn;
#pragma unroll
            for (int off = 16; off; off >>= 1)
                m = fmaxf(m, __shfl_xor_sync(0xffffffffu, m, off));
            float e = __expf(bn - m);
            float ssum = e;
#pragma unroll
            for (int off = 16; off; off >>= 1)
                ssum += __shfl_xor_sync(0xffffffffu, ssum, off);
            c = e / ssum;
        }
#pragma unroll
        for (int d = 0; d < 16; d++) acc[d] = fmaf(c, u[d], acc[d]);
    }

    // cross-warp reduce via padded smem atomics (bank-conflict-free)
#pragma unroll
    for (int d = 0; d < 16; d++) atomicAdd(&sacc[j][d], acc[d]);
    __syncthreads();

    // one partial per CTA -> global (spread atomics, 32 hits/address total)
    for (int e = threadIdx.x; e < JD; e += 256) {
        int jj = e >> 4, dd = e & 15;
        atomicAdd(&g_s[(b * J + jj) * D + dd], sacc[jj][dd]);
    }
}

// ---------------------------------------------------------------------------
// Kernel 3: squash. out==nullptr -> write g_v and zero s for the next pass;
// else write final result to out.
// ---------------------------------------------------------------------------
__global__ void squash_k(float* out) {
    int bj = blockIdx.x * blockDim.x + threadIdx.x;
    if (bj >= B * J) return;
    float4* sp = reinterpret_cast<float4*>(g_s + bj * D);
    float4 s0 = sp[0], s1 = sp[1], s2 = sp[2], s3 = sp[3];
    float n2 = 1e-7f
        + s0.x*s0.x + s0.y*s0.y + s0.z*s0.z + s0.w*s0.w
        + s1.x*s1.x + s1.y*s1.y + s1.z*s1.z + s1.w*s1.w
        + s2.x*s2.x + s2.y*s2.y + s2.z*s2.z + s2.w*s2.w
        + s3.x*s3.x + s3.y*s3.y + s3.z*s3.z + s3.w*s3.w;
    float scale = n2 / ((1.f + n2) * sqrtf(n2));

    float4 o0 = make_float4(s0.x*scale, s0.y*scale, s0.z*scale, s0.w*scale);
    float4 o1 = make_float4(s1.x*scale, s1.y*scale, s1.z*scale, s1.w*scale);
    float4 o2 = make_float4(s2.x*scale, s2.y*scale, s2.z*scale, s2.w*scale);
    float4 o3 = make_float4(s3.x*scale, s3.y*scale, s3.z*scale, s3.w*scale);

    if (out) {
        float4* op = reinterpret_cast<float4*>(out + bj * D);
        op[0] = o0; op[1] = o1; op[2] = o2; op[3] = o3;
    } else {
        float4* op = reinterpret_cast<float4*>(g_v + bj * D);
        op[0] = o0; op[1] = o1; op[2] = o2; op[3] = o3;
        float4 z = make_float4(0.f, 0.f, 0.f, 0.f);
        sp[0] = z; sp[1] = z; sp[2] = z; sp[3] = z;    // zero s for next pass
    }
}

__global__ void zero_s_k() {
    int t = blockIdx.x * blockDim.x + threadIdx.x;
    if (t < B * J * D) g_s[t] = 0.f;
}

// ---------------------------------------------------------------------------
extern "C" void kernel_launch(void* const* d_in, const int* in_sizes, int n_in,
                              void* d_out, int out_size) {
    const float* in = (const float*)d_in[0];   // [B, I, P]
    const float* W  = (const float*)d_in[1];   // [I, J, 16, 16] -> [i, jd, p]
    float* out = (float*)d_out;                // [B, J, D]
    (void)in_sizes; (void)n_in; (void)out_size;

    zero_s_k<<<32, 1024>>>();                  // replay-safe s init
    gemm_uhat<<<I, 256>>>(in, W);

    dim3 rg(NIB, B);
    routing_step<0><<<rg, 256>>>();            // r=0: uniform c
    squash_k<<<8, 256>>>(nullptr);             // v0, zero s

    routing_step<1><<<rg, 256>>>();            // r=1: b1 = u.v0, c=softmax
    squash_k<<<8, 256>>>(nullptr);             // v1, zero s

    routing_step<2><<<rg, 256>>>();            // r=2: b2 = b1 + u.v1
    squash_k<<<8, 256>>>(out);                 // final v -> d_out
}